// round 4
// baseline (speedup 1.0000x reference)
#include <cuda_runtime.h>
#include <cstdint>

// ---------------------------------------------------------------------------
// Problem constants
// ---------------------------------------------------------------------------
#define NB    8
#define NC    512     // CIN = COUT = WDIM = 512
#define SQRT2F 1.4142135623730951f
#define INV_SQRT512 0.044194173824159216f
#define CLAMPV 256.0f

// x output elements: 8*512*64*64
#define XOUT_ELEMS (8*512*64*64)

// ---------------------------------------------------------------------------
// Scratch (static device globals -- no allocation at runtime)
// ---------------------------------------------------------------------------
__device__ float g_s0[NB*NC];
__device__ float g_s1[NB*NC];
__device__ float g_srgb[NB*NC];
__device__ float g_d0[NB*NC];
__device__ float g_d1[NB*NC];
__device__ float g_wm[NB*3*NC];
__device__ float g_W20T[NC*NC];          // sum_k w0^2, transposed [i][o]
__device__ float g_W21T[NC*NC];
__device__ float g_wt0[NC*9*NC];         // weight0 transposed to [i][tap][o]
__device__ float g_wt1[NC*9*NC];
__device__ float g_xm[NB*NC*32*32];      // x * s0
__device__ float g_u[(size_t)NB*NC*65*65];   // conv-transpose output (pre-blur)
__device__ float g_x1m[(size_t)NB*NC*64*64]; // act(blk0) * s1

// ---------------------------------------------------------------------------
// f32x2 packed math helpers
// ---------------------------------------------------------------------------
__device__ __forceinline__ unsigned long long pack2(float lo, float hi) {
    unsigned long long r;
    asm("mov.b64 %0, {%1, %2};" : "=l"(r) : "f"(lo), "f"(hi));
    return r;
}
__device__ __forceinline__ unsigned long long ffma2(unsigned long long a,
                                                    unsigned long long b,
                                                    unsigned long long c) {
    unsigned long long d;
    asm("fma.rn.f32x2 %0, %1, %2, %3;" : "=l"(d) : "l"(a), "l"(b), "l"(c));
    return d;
}
__device__ __forceinline__ float2 unpack2(unsigned long long v) {
    float2 f;
    asm("mov.b64 {%0, %1}, %2;" : "=f"(f.x), "=f"(f.y) : "l"(v));
    return f;
}

__device__ __forceinline__ float act_lrelu_clamp(float v) {
    v = (v < 0.f ? 0.2f * v : v) * SQRT2F;
    return fminf(fmaxf(v, -CLAMPV), CLAMPV);
}

// ---------------------------------------------------------------------------
// K1: styles (3 affines).  grid (8, 3), block 512
// ---------------------------------------------------------------------------
__global__ void styles_kernel(const float* __restrict__ ws,
                              const float* __restrict__ a0w, const float* __restrict__ a0b,
                              const float* __restrict__ a1w, const float* __restrict__ a1b,
                              const float* __restrict__ arw, const float* __restrict__ arb) {
    int b = blockIdx.x, l = blockIdx.y, o = threadIdx.x;
    __shared__ float sw[NC];
    sw[o] = ws[(b * 3 + l) * NC + o];
    __syncthreads();
    const float* A  = (l == 0) ? a0w : (l == 1) ? a1w : arw;
    const float* Ab = (l == 0) ? a0b : (l == 1) ? a1b : arb;
    const float* Arow = A + (size_t)o * NC;
    float s = 0.f;
#pragma unroll 8
    for (int i = 0; i < NC; i++) s += sw[i] * Arow[i];
    s = s * INV_SQRT512 + Ab[o];
    float* dst = (l == 0) ? g_s0 : (l == 1) ? g_s1 : g_srgb;
    dst[b * NC + o] = s;
}

// ---------------------------------------------------------------------------
// K2: W2 = sum over 9 taps of weight^2, stored transposed [i][o].
// ---------------------------------------------------------------------------
__global__ void w2_kernel(const float* __restrict__ w0, const float* __restrict__ w1) {
    int o = blockIdx.x, i = threadIdx.x;
    const float* p0 = w0 + ((size_t)o * NC + i) * 9;
    const float* p1 = w1 + ((size_t)o * NC + i) * 9;
    float a0 = 0.f, a1 = 0.f;
#pragma unroll
    for (int t = 0; t < 9; t++) { a0 += p0[t] * p0[t]; a1 += p1[t] * p1[t]; }
    g_W20T[i * NC + o] = a0;
    g_W21T[i * NC + o] = a1;
}

// ---------------------------------------------------------------------------
// K2b: transpose weights to [i][tap][o] for coalesced smem staging in conv.
// ---------------------------------------------------------------------------
__global__ void wtr_kernel(const float* __restrict__ w0, const float* __restrict__ w1) {
    int idx = blockIdx.x * 256 + threadIdx.x;   // over 512*9*512 dst elements
    if (idx >= NC * 9 * NC) return;
    int o = idx & (NC - 1);
    int t = (idx >> 9) % 9;
    int i = (idx >> 9) / 9;
    size_t src = ((size_t)o * NC + i) * 9 + t;
    g_wt0[idx] = w0[src];
    g_wt1[idx] = w1[src];
}

// ---------------------------------------------------------------------------
// K3: demodulation  d[b,o] = rsqrt(sum_i W2T[i,o] * s[b,i]^2 + 1e-8)
// ---------------------------------------------------------------------------
__global__ void demod_kernel() {
    int b = blockIdx.x, which = blockIdx.y, o = threadIdx.x;
    const float* s  = which ? g_s1 : g_s0;
    const float* W2 = which ? g_W21T : g_W20T;
    __shared__ float ss[NC];
    float sv = s[b * NC + o];
    ss[o] = sv * sv;
    __syncthreads();
    float acc = 0.f;
#pragma unroll 8
    for (int i = 0; i < NC; i++) acc += W2[i * NC + o] * ss[i];
    acc += 1e-8f;
    float r = rsqrtf(acc);
    r = r * (1.5f - 0.5f * acc * r * r);   // Newton refine
    (which ? g_d1 : g_d0)[b * NC + o] = r;
}

// ---------------------------------------------------------------------------
// K3b: ToRGB weights  wm[b,c,o] = weight_rgb[c,o] * srgb[b,o] / sqrt(512)
// ---------------------------------------------------------------------------
__global__ void wm_kernel(const float* __restrict__ wrgb) {
    int b = blockIdx.x, o = threadIdx.x;
    float sr = g_srgb[b * NC + o] * INV_SQRT512;
#pragma unroll
    for (int c = 0; c < 3; c++)
        g_wm[(b * 3 + c) * NC + o] = wrgb[c * NC + o] * sr;
}

// ---------------------------------------------------------------------------
// K4: xm = x * s0 (per input channel)
// ---------------------------------------------------------------------------
__global__ void xm_kernel(const float* __restrict__ x) {
    int idx = blockIdx.x * 256 + threadIdx.x;
    if (idx >= NB * NC * 1024) return;
    int ch = (idx >> 10) & (NC - 1);
    int b  = idx >> 19;
    g_xm[idx] = x[idx] * g_s0[b * NC + ch];
}

// ---------------------------------------------------------------------------
// Unified conv kernel.  Block: 64 oc x 16x16 px, 256 thr, 8oc x 8px / thread
// as f32x2 oc-pairs.
// MODE 0: in=g_xm,  w=g_wt0, d=g_d0, out=g_u   (conv-transpose parity)
// MODE 1: in=g_x1m, w=g_wt1, d=g_d1, out=outp  (main conv + noise/bias/act)
// ---------------------------------------------------------------------------
template<int KH, int KW, int FLIP, int IOFF,
         int WY0, int WYS, int WX0, int WXS,
         int IH, int IW, int OH, int OW,
         int OSTR, int OOY, int OOX, int OSH, int OSW, int MODE>
__global__ void __launch_bounds__(256)
conv_core(float* __restrict__ outp,
          const float* __restrict__ bias, const float* __restrict__ noise,
          const float* __restrict__ nsp) {
    constexpr int KC  = 8;
    constexpr int SH  = KH + 15;
    constexpr int SWT = KW + 15;
    constexpr int NTX = (OW + 15) / 16;

    const float* __restrict__ in   = (MODE == 0) ? g_xm  : g_x1m;
    const float* __restrict__ wt   = (MODE == 0) ? g_wt0 : g_wt1;
    const float* __restrict__ dvec = (MODE == 0) ? g_d0  : g_d1;
    float* __restrict__ out        = (MODE == 0) ? g_u   : outp;

    __shared__ __align__(16) float sX[KC][SH][20];
    __shared__ __align__(16) float sW[KC][KH * KW][64];

    const int tid   = threadIdx.x;
    const int colh  = tid & 1;
    const int lrow  = (tid >> 1) & 15;
    const int ocg   = tid >> 5;           // 0..7 (constant per warp)
    const int c0    = colh * 8;

    const int b      = blockIdx.z;
    const int obase  = blockIdx.y * 64;
    const int ty     = blockIdx.x / NTX;
    const int tx     = blockIdx.x % NTX;
    const int tileY0 = ty * 16;
    const int tileX0 = tx * 16;
    const int SROW0  = tileY0 + (FLIP ? -(KH - 1) : IOFF);
    const int SCOL0  = tileX0 + (FLIP ? -(KW - 1) : IOFF);

    unsigned long long acc[4][8];
#pragma unroll
    for (int p = 0; p < 4; p++)
#pragma unroll
        for (int q = 0; q < 8; q++) acc[p][q] = 0ull;

    for (int cb = 0; cb < NC; cb += KC) {
        __syncthreads();
        // stage input tile (zero-padded)
        for (int idx = tid; idx < KC * SH * SWT; idx += 256) {
            int c   = idx / (SH * SWT);
            int rem = idx % (SH * SWT);
            int r = rem / SWT, s = rem % SWT;
            int gy = SROW0 + r, gx = SCOL0 + s;
            float v = 0.f;
            if (gy >= 0 && gy < IH && gx >= 0 && gx < IW)
                v = in[(((size_t)b * NC + cb + c) * IH + gy) * IW + gx];
            sX[c][r][s] = v;
        }
        // stage weights [c][tap][oc] from transposed global layout [i][t][o]
        for (int idx = tid; idx < KC * KH * KW * 64; idx += 256) {
            int o   = idx & 63;
            int rem = idx >> 6;
            int k = rem % (KH * KW);
            int c = rem / (KH * KW);
            int ky = k / KW, kx = k % KW;
            int t = (WY0 + WYS * ky) * 3 + (WX0 + WXS * kx);
            sW[c][k][o] = wt[((size_t)(cb + c) * 9 + t) * NC + obase + o];
        }
        __syncthreads();

#pragma unroll 1
        for (int c = 0; c < KC; c++) {
#pragma unroll
            for (int ky = 0; ky < KH; ky++) {
                const int r = lrow + (FLIP ? (KH - 1 - ky) : ky);
                const float* xr = &sX[c][r][c0];
                float4 A4 = *(const float4*)(xr);
                float4 B4 = *(const float4*)(xr + 4);
                float4 C4 = *(const float4*)(xr + 8);
                float xw[12] = {A4.x, A4.y, A4.z, A4.w,
                                B4.x, B4.y, B4.z, B4.w,
                                C4.x, C4.y, C4.z, C4.w};
                unsigned long long xp[KW + 7];
#pragma unroll
                for (int j = 0; j < KW + 7; j++) xp[j] = pack2(xw[j], xw[j]);
#pragma unroll
                for (int kx = 0; kx < KW; kx++) {
                    const int k   = ky * KW + kx;
                    const int off = FLIP ? (KW - 1 - kx) : kx;
                    ulonglong2 wA = *(const ulonglong2*)&sW[c][k][ocg * 8];
                    ulonglong2 wB = *(const ulonglong2*)&sW[c][k][ocg * 8 + 4];
#pragma unroll
                    for (int px = 0; px < 8; px++) {
                        unsigned long long xv = xp[off + px];
                        acc[0][px] = ffma2(wA.x, xv, acc[0][px]);
                        acc[1][px] = ffma2(wA.y, xv, acc[1][px]);
                        acc[2][px] = ffma2(wB.x, xv, acc[2][px]);
                        acc[3][px] = ffma2(wB.y, xv, acc[3][px]);
                    }
                }
            }
        }
    }

    // epilogue
    const int oy = tileY0 + lrow;
    if (oy >= OH) return;
    float nsv = 0.f;
    if (MODE == 1) nsv = *nsp;
    float dv[8];
#pragma unroll
    for (int j = 0; j < 8; j++) dv[j] = dvec[b * NC + obase + ocg * 8 + j];

#pragma unroll
    for (int pr = 0; pr < 4; pr++) {
#pragma unroll
        for (int px = 0; px < 8; px++) {
            int ox = tileX0 + c0 + px;
            if (ox >= OW) continue;
            float2 v2 = unpack2(acc[pr][px]);
            int Y = oy * OSTR + OOY;
            int X = ox * OSTR + OOX;
#pragma unroll
            for (int e = 0; e < 2; e++) {
                int oc = ocg * 8 + pr * 2 + e;
                float v = (e ? v2.y : v2.x) * dv[pr * 2 + e];
                if (MODE == 1) {
                    v += noise[oy * 64 + ox] * nsv + bias[obase + oc];
                    v = act_lrelu_clamp(v);
                }
                out[(((size_t)b * NC + obase + oc) * OSH + Y) * OSW + X] = v;
            }
        }
    }
}

// ---------------------------------------------------------------------------
// K6: 4x4 blur (gain 4) on g_u[65,65] -> 64x64, + noise0 + bias0 + act, * s1
// ---------------------------------------------------------------------------
__global__ void __launch_bounds__(256) blur_kernel(
        const float* __restrict__ nc0, const float* __restrict__ ns0p,
        const float* __restrict__ bias0) {
    __shared__ float su[19][20];
    int b = blockIdx.z, ch = blockIdx.y;
    int ty = blockIdx.x >> 2, tx = blockIdx.x & 3;
    int Y0 = ty * 16, X0 = tx * 16;
    const float* up = g_u + ((size_t)b * NC + ch) * 65 * 65;
    for (int idx = threadIdx.x; idx < 19 * 19; idx += 256) {
        int r = idx / 19, s = idx % 19;
        int gy = Y0 - 1 + r, gx = X0 - 1 + s;
        su[r][s] = (gy >= 0 && gy < 65 && gx >= 0 && gx < 65) ? up[gy * 65 + gx] : 0.f;
    }
    __syncthreads();
    int ly = threadIdx.x >> 4, lx = threadIdx.x & 15;
    const float G[4] = {0.25f, 0.75f, 0.75f, 0.25f};
    float acc = 0.f;
#pragma unroll
    for (int a = 0; a < 4; a++) {
        float rowacc = 0.f;
#pragma unroll
        for (int bb = 0; bb < 4; bb++) rowacc += su[ly + a][lx + bb] * G[bb];
        acc += rowacc * G[a];
    }
    int y = Y0 + ly, x = X0 + lx;
    float v = acc + nc0[y * 64 + x] * (*ns0p) + bias0[ch];
    v = act_lrelu_clamp(v);
    g_x1m[((size_t)b * NC + ch) * 4096 + y * 64 + x] = v * g_s1[b * NC + ch];
}

// ---------------------------------------------------------------------------
// K9+K10: img upsample (depthwise, lhs_dilation 2) + ToRGB + add.
// ---------------------------------------------------------------------------
__global__ void __launch_bounds__(256) torgb_kernel(
        const float* __restrict__ x2, const float* __restrict__ img,
        const float* __restrict__ brgb, float* __restrict__ imgout) {
    __shared__ float swm[3 * NC];
    int b = blockIdx.y;
    for (int i = threadIdx.x; i < 3 * NC; i += 256) swm[i] = g_wm[b * 3 * NC + i];
    __syncthreads();
    int pxl = blockIdx.x * 256 + threadIdx.x;       // 0..4095
    int Y = pxl >> 6, X = pxl & 63;

    float a0 = 0.f, a1 = 0.f, a2 = 0.f;
    const float* xp = x2 + (size_t)b * NC * 4096 + pxl;
#pragma unroll 8
    for (int o = 0; o < NC; o++) {
        float xv = xp[(size_t)o * 4096];
        a0 += xv * swm[o];
        a1 += xv * swm[NC + o];
        a2 += xv * swm[2 * NC + o];
    }

    const float G[4] = {0.25f, 0.75f, 0.75f, 0.25f};
    float up0 = 0.f, up1 = 0.f, up2 = 0.f;
#pragma unroll
    for (int a = 0; a < 4; a++) {
        int yy = Y + a - 2;
        if (yy & 1) continue;
        int iy = yy >> 1;
        if (iy < 0 || iy > 31) continue;
#pragma unroll
        for (int bb = 0; bb < 4; bb++) {
            int xx = X + bb - 2;
            if (xx & 1) continue;
            int ix = xx >> 1;
            if (ix < 0 || ix > 31) continue;
            float cf = G[a] * G[bb];
            up0 += img[((size_t)(b * 3 + 0) * 32 + iy) * 32 + ix] * cf;
            up1 += img[((size_t)(b * 3 + 1) * 32 + iy) * 32 + ix] * cf;
            up2 += img[((size_t)(b * 3 + 2) * 32 + iy) * 32 + ix] * cf;
        }
    }
    float y0 = fminf(fmaxf(a0 + brgb[0], -CLAMPV), CLAMPV);
    float y1 = fminf(fmaxf(a1 + brgb[1], -CLAMPV), CLAMPV);
    float y2 = fminf(fmaxf(a2 + brgb[2], -CLAMPV), CLAMPV);
    imgout[((size_t)b * 3 + 0) * 4096 + pxl] = up0 + y0;
    imgout[((size_t)b * 3 + 1) * 4096 + pxl] = up1 + y1;
    imgout[((size_t)b * 3 + 2) * 4096 + pxl] = up2 + y2;
}

// ---------------------------------------------------------------------------
// Launch
// ---------------------------------------------------------------------------
extern "C" void kernel_launch(void* const* d_in, const int* in_sizes, int n_in,
                              void* d_out, int out_size) {
    (void)in_sizes; (void)n_in; (void)out_size;
    const float* x    = (const float*)d_in[0];
    const float* img  = (const float*)d_in[1];
    const float* ws   = (const float*)d_in[2];
    const float* a0w  = (const float*)d_in[3];
    const float* a0b  = (const float*)d_in[4];
    const float* w0   = (const float*)d_in[5];
    const float* b0   = (const float*)d_in[6];
    const float* ns0  = (const float*)d_in[7];
    const float* a1w  = (const float*)d_in[8];
    const float* a1b  = (const float*)d_in[9];
    const float* w1   = (const float*)d_in[10];
    const float* b1   = (const float*)d_in[11];
    const float* ns1  = (const float*)d_in[12];
    const float* arw  = (const float*)d_in[13];
    const float* arb  = (const float*)d_in[14];
    const float* wrgb = (const float*)d_in[15];
    const float* brgb = (const float*)d_in[16];
    const float* nc0  = (const float*)d_in[17];
    const float* nc1  = (const float*)d_in[18];

    float* xout   = (float*)d_out;
    float* imgout = (float*)d_out + XOUT_ELEMS;

    // prologue (tiny)
    styles_kernel<<<dim3(NB, 3), NC>>>(ws, a0w, a0b, a1w, a1b, arw, arb);
    w2_kernel<<<NC, NC>>>(w0, w1);
    wtr_kernel<<<(NC * 9 * NC + 255) / 256, 256>>>(w0, w1);
    demod_kernel<<<dim3(NB, 2), NC>>>();
    wm_kernel<<<NB, NC>>>(wrgb);
    xm_kernel<<<(NB * NC * 1024 + 255) / 256, 256>>>(x);

    // conv-transpose as 4 parity sub-convs writing interleaved into g_u[65,65]
    conv_core<2,2,1,0, 0,2,0,2, 32,32, 33,33, 2,0,0, 65,65, 0>
        <<<dim3(3*3, 8, NB), 256>>>(nullptr, nullptr, nullptr, nullptr);
    conv_core<2,1,1,0, 0,2,1,2, 32,32, 33,32, 2,0,1, 65,65, 0>
        <<<dim3(2*3, 8, NB), 256>>>(nullptr, nullptr, nullptr, nullptr);
    conv_core<1,2,1,0, 1,2,0,2, 32,32, 32,33, 2,1,0, 65,65, 0>
        <<<dim3(3*2, 8, NB), 256>>>(nullptr, nullptr, nullptr, nullptr);
    conv_core<1,1,1,0, 1,2,1,2, 32,32, 32,32, 2,1,1, 65,65, 0>
        <<<dim3(2*2, 8, NB), 256>>>(nullptr, nullptr, nullptr, nullptr);

    // blur + noise0 + bias0 + act, fold s1 -> g_x1m
    blur_kernel<<<dim3(16, NC, NB), 256>>>(nc0, ns0, b0);

    // main 3x3 conv + noise1 + bias1 + act -> d_out (x part)
    conv_core<3,3,0,-1, 0,1,0,1, 64,64, 64,64, 1,0,0, 64,64, 1>
        <<<dim3(16, 8, NB), 256>>>(xout, b1, nc1, ns1);

    // img upsample + ToRGB
    torgb_kernel<<<dim3(16, NB), 256>>>(xout, img, brgb, imgout);
}

// round 7
// speedup vs baseline: 1.2408x; 1.2408x over previous
#include <cuda_runtime.h>
#include <cuda_bf16.h>
#include <mma.h>
#include <cstdint>

using namespace nvcuda;

// ---------------------------------------------------------------------------
// Problem constants
// ---------------------------------------------------------------------------
#define NB    8
#define NC    512
#define SQRT2F 1.4142135623730951f
#define INV_SQRT512 0.044194173824159216f
#define CLAMPV 256.0f
#define XOUT_ELEMS (8*512*64*64)

// ---------------------------------------------------------------------------
// Scratch (static device globals)
// ---------------------------------------------------------------------------
__device__ float g_s0[NB*NC];
__device__ float g_s1[NB*NC];
__device__ float g_srgb[NB*NC];
__device__ float g_d0[NB*NC];
__device__ float g_d1[NB*NC];
__device__ float g_wm[NB*3*NC];
__device__ float g_W20T[NC*NC];
__device__ float g_W21T[NC*NC];

// bf16 hi/lo split tensors (16B aligned for uint4 access)
__device__ __align__(16) __nv_bfloat16 g_W0h[4*9*NC*NC];  // convT eff weights [par][tap][o][i]
__device__ __align__(16) __nv_bfloat16 g_W0l[4*9*NC*NC];
__device__ __align__(16) __nv_bfloat16 g_W1h[9*NC*NC];    // conv1 weights [tap][o][i]
__device__ __align__(16) __nv_bfloat16 g_W1l[9*NC*NC];
__device__ __align__(16) __nv_bfloat16 g_x0h[NB*32*32*NC];  // x*s0, NHWC
__device__ __align__(16) __nv_bfloat16 g_x0l[NB*32*32*NC];
__device__ __align__(16) __nv_bfloat16 g_x1h[(size_t)NB*64*64*NC]; // act(blk0)*s1, NHWC
__device__ __align__(16) __nv_bfloat16 g_x1l[(size_t)NB*64*64*NC];

__device__ __forceinline__ float act_lrelu_clamp(float v) {
    v = (v < 0.f ? 0.2f * v : v) * SQRT2F;
    return fminf(fmaxf(v, -CLAMPV), CLAMPV);
}

// ---------------------------------------------------------------------------
// Prologue kernels
// ---------------------------------------------------------------------------
__global__ void styles_kernel(const float* __restrict__ ws,
                              const float* __restrict__ a0w, const float* __restrict__ a0b,
                              const float* __restrict__ a1w, const float* __restrict__ a1b,
                              const float* __restrict__ arw, const float* __restrict__ arb) {
    int b = blockIdx.x, l = blockIdx.y, o = threadIdx.x;
    __shared__ float sw[NC];
    sw[o] = ws[(b * 3 + l) * NC + o];
    __syncthreads();
    const float* A  = (l == 0) ? a0w : (l == 1) ? a1w : arw;
    const float* Ab = (l == 0) ? a0b : (l == 1) ? a1b : arb;
    const float* Arow = A + (size_t)o * NC;
    float s = 0.f;
#pragma unroll 8
    for (int i = 0; i < NC; i++) s += sw[i] * Arow[i];
    s = s * INV_SQRT512 + Ab[o];
    float* dst = (l == 0) ? g_s0 : (l == 1) ? g_s1 : g_srgb;
    dst[b * NC + o] = s;
}

__global__ void w2_kernel(const float* __restrict__ w0, const float* __restrict__ w1) {
    int o = blockIdx.x, i = threadIdx.x;
    const float* p0 = w0 + ((size_t)o * NC + i) * 9;
    const float* p1 = w1 + ((size_t)o * NC + i) * 9;
    float a0 = 0.f, a1 = 0.f;
#pragma unroll
    for (int t = 0; t < 9; t++) { a0 += p0[t] * p0[t]; a1 += p1[t] * p1[t]; }
    g_W20T[i * NC + o] = a0;
    g_W21T[i * NC + o] = a1;
}

__global__ void demod_kernel() {
    int b = blockIdx.x, which = blockIdx.y, o = threadIdx.x;
    const float* s  = which ? g_s1 : g_s0;
    const float* W2 = which ? g_W21T : g_W20T;
    __shared__ float ss[NC];
    float sv = s[b * NC + o];
    ss[o] = sv * sv;
    __syncthreads();
    float acc = 0.f;
#pragma unroll 8
    for (int i = 0; i < NC; i++) acc += W2[i * NC + o] * ss[i];
    acc += 1e-8f;
    float r = rsqrtf(acc);
    r = r * (1.5f - 0.5f * acc * r * r);
    (which ? g_d1 : g_d0)[b * NC + o] = r;
}

__global__ void wm_kernel(const float* __restrict__ wrgb) {
    int b = blockIdx.x, o = threadIdx.x;
    float sr = g_srgb[b * NC + o] * INV_SQRT512;
#pragma unroll
    for (int c = 0; c < 3; c++)
        g_wm[(b * 3 + c) * NC + o] = wrgb[c * NC + o] * sr;
}

// w1[o][i][3][3] -> [tap][o][i] bf16 hi/lo
__global__ void prep_w1_kernel(const float* __restrict__ w1) {
    int idx = blockIdx.x * 256 + threadIdx.x;
    if (idx >= 9 * NC * NC) return;
    int i = idx & (NC - 1);
    int o = (idx >> 9) & (NC - 1);
    int tap = idx >> 18;
    float v = w1[((size_t)o * NC + i) * 9 + tap];
    __nv_bfloat16 hi = __float2bfloat16(v);
    __nv_bfloat16 lo = __float2bfloat16(v - __bfloat162float(hi));
    g_W1h[idx] = hi;
    g_W1l[idx] = lo;
}

// fold 4x4 blur (gain 4) into stride-2 transpose weights; parity-decompose.
__global__ void prep_w0eff_kernel(const float* __restrict__ w0) {
    int idx = blockIdx.x * 256 + threadIdx.x;
    if (idx >= NC * NC) return;
    int i = idx & (NC - 1);
    int o = idx >> 9;
    float w[3][3];
#pragma unroll
    for (int k = 0; k < 9; k++) w[k / 3][k % 3] = w0[((size_t)o * NC + i) * 9 + k];
    const float G[4] = {0.25f, 0.75f, 0.75f, 0.25f};
    float K[6][6];
#pragma unroll
    for (int my = -2; my <= 3; my++) {
#pragma unroll
        for (int mx = -2; mx <= 3; mx++) {
            float a = 0.f;
#pragma unroll
            for (int jy = 0; jy < 4; jy++) {
                int ry = my - 1 + jy;
                if (ry < 0 || ry > 2) continue;
#pragma unroll
                for (int jx = 0; jx < 4; jx++) {
                    int rx = mx - 1 + jx;
                    if (rx < 0 || rx > 2) continue;
                    a += G[jy] * G[jx] * w[ry][rx];
                }
            }
            K[my + 2][mx + 2] = a;
        }
    }
#pragma unroll
    for (int ey = 0; ey < 2; ey++)
#pragma unroll
    for (int ex = 0; ex < 2; ex++)
#pragma unroll
    for (int dy = -1; dy <= 1; dy++)
#pragma unroll
    for (int dx = -1; dx <= 1; dx++) {
        float v = K[2 * dy + ey + 2][2 * dx + ex + 2];
        __nv_bfloat16 hi = __float2bfloat16(v);
        __nv_bfloat16 lo = __float2bfloat16(v - __bfloat162float(hi));
        size_t dst = ((size_t)((ey * 2 + ex) * 9 + (dy + 1) * 3 + (dx + 1)) * NC + o) * NC + i;
        g_W0h[dst] = hi;
        g_W0l[dst] = lo;
    }
}

// x NCHW fp32 * s0 -> NHWC bf16 hi/lo
__global__ void prep_x0_kernel(const float* __restrict__ x) {
    __shared__ float sm[32][33];
    int cb = blockIdx.x, y = blockIdx.y, b = blockIdx.z;
    int t = threadIdx.x;
#pragma unroll
    for (int it = 0; it < 4; it++) {
        int cc = (t >> 5) + it * 8;
        int xx = t & 31;
        int ch = cb * 32 + cc;
        sm[cc][xx] = x[((size_t)(b * NC + ch) * 32 + y) * 32 + xx] * g_s0[b * NC + ch];
    }
    __syncthreads();
#pragma unroll
    for (int it = 0; it < 4; it++) {
        int xx = (t >> 5) + it * 8;
        int cc = t & 31;
        float v = sm[cc][xx];
        __nv_bfloat16 hi = __float2bfloat16(v);
        __nv_bfloat16 lo = __float2bfloat16(v - __bfloat162float(hi));
        size_t dst = ((size_t)(b * 32 + y) * 32 + xx) * NC + cb * 32 + cc;
        g_x0h[dst] = hi;
        g_x0l[dst] = lo;
    }
}

// ---------------------------------------------------------------------------
// WMMA bf16 3-pass implicit-GEMM conv kernel (both convs).
// CTA: D[128 oc x 128 px]; K = 512 ic x 9 taps, staged 64 ic/stage.
// 8 warps: warp (wm = wid&3, wn = wid>>2) owns oc [wm*32,+32) x px [wn*64,+64)
// CONVT=1: g_x0 32x32 -> g_x1 NHWC bf16 (fused blur/noise0/bias0/act/s1)
// CONVT=0: g_x1 64x64 -> xout NCHW fp32 (fused noise1/bias1/act)
// ---------------------------------------------------------------------------
#define KCH   64           // ic per stage
#define LDS_T 72           // bf16 stage stride (144B, 16B-multiple)
#define LDS_F 132          // fp32 epilogue stride (528B, 16B-multiple)

template<int CONVT>
__global__ void __launch_bounds__(256) mma_conv_kernel(
        const float* __restrict__ noisec, const float* __restrict__ nsp,
        const float* __restrict__ biasp, float* __restrict__ xout) {
    extern __shared__ __align__(16) char dsm[];
    __nv_bfloat16* sAh = (__nv_bfloat16*)dsm;                    // 128 x LDS_T
    __nv_bfloat16* sAl = (__nv_bfloat16*)(dsm + 18432);
    __nv_bfloat16* sBh = (__nv_bfloat16*)(dsm + 36864);
    __nv_bfloat16* sBl = (__nv_bfloat16*)(dsm + 55296);

    const int tid = threadIdx.x;
    const int wid = tid >> 5;
    const int wm = wid & 3;          // oc group (32 rows)
    const int wn = wid >> 2;         // px group (64 cols)

    const int b = blockIdx.z;
    int par = 0, ocb, tY0, tX0;
    if (CONVT) {
        par = blockIdx.y >> 2; ocb = blockIdx.y & 3;
        tY0 = (blockIdx.x >> 1) * 8; tX0 = (blockIdx.x & 1) * 16;
    } else {
        ocb = blockIdx.y;
        tY0 = (blockIdx.x >> 2) * 8; tX0 = (blockIdx.x & 3) * 16;
    }
    const int obase = ocb * 128;
    const int IHW = CONVT ? 32 : 64;

    const __nv_bfloat16* __restrict__ Wh = CONVT ? g_W0h + (size_t)par * 9 * NC * NC : g_W1h;
    const __nv_bfloat16* __restrict__ Wl = CONVT ? g_W0l + (size_t)par * 9 * NC * NC : g_W1l;
    const __nv_bfloat16* __restrict__ Xh = CONVT ? g_x0h + (size_t)b * 32 * 32 * NC
                                                 : g_x1h + (size_t)b * 64 * 64 * NC;
    const __nv_bfloat16* __restrict__ Xl = CONVT ? g_x0l + (size_t)b * 32 * 32 * NC
                                                 : g_x1l + (size_t)b * 64 * 64 * NC;

    wmma::fragment<wmma::accumulator, 16, 16, 16, float> acc[2][4];
#pragma unroll
    for (int m = 0; m < 2; m++)
#pragma unroll
        for (int n = 0; n < 4; n++) wmma::fill_fragment(acc[m][n], 0.f);

    for (int tap = 0; tap < 9; tap++) {
        const int oy = CONVT ? (1 - tap / 3) : (tap / 3 - 1);
        const int ox = CONVT ? (1 - tap % 3) : (tap % 3 - 1);
        for (int icb = 0; icb < NC; icb += KCH) {
            __syncthreads();
            // stage A (weights): 128 oc x 64 ic hi/lo
            for (int idx = tid; idx < 1024; idx += 256) {
                int r = idx >> 3, c16 = idx & 7;
                size_t src = ((size_t)tap * NC + obase + r) * NC + icb + c16 * 8;
                int dst = r * LDS_T + c16 * 8;
                *(uint4*)(sAh + dst) = *(const uint4*)(Wh + src);
                *(uint4*)(sAl + dst) = *(const uint4*)(Wl + src);
            }
            // stage B (input pixels): 128 px x 64 ic hi/lo, zero-pad OOB
            for (int idx = tid; idx < 1024; idx += 256) {
                int p = idx >> 3, c16 = idx & 7;
                int ly = p >> 4, lx = p & 15;
                int iy = tY0 + ly + oy, ix = tX0 + lx + ox;
                uint4 vh = make_uint4(0, 0, 0, 0), vl = make_uint4(0, 0, 0, 0);
                if (iy >= 0 && iy < IHW && ix >= 0 && ix < IHW) {
                    size_t src = ((size_t)iy * IHW + ix) * NC + icb + c16 * 8;
                    vh = *(const uint4*)(Xh + src);
                    vl = *(const uint4*)(Xl + src);
                }
                int dst = p * LDS_T + c16 * 8;
                *(uint4*)(sBh + dst) = vh;
                *(uint4*)(sBl + dst) = vl;
            }
            __syncthreads();

#pragma unroll
            for (int k16 = 0; k16 < KCH / 16; k16++) {
                const int ko = k16 * 16;
                const __nv_bfloat16* pA = sAh + (wm * 32) * LDS_T + ko;
                const __nv_bfloat16* pB = sBh + (wn * 64) * LDS_T + ko;

                wmma::fragment<wmma::matrix_a, 16, 16, 16, __nv_bfloat16, wmma::row_major> ah[2], al[2];
                wmma::fragment<wmma::matrix_b, 16, 16, 16, __nv_bfloat16, wmma::col_major> bh[4], bl[4];
#pragma unroll
                for (int m = 0; m < 2; m++)
                    wmma::load_matrix_sync(ah[m], pA + m * 16 * LDS_T, LDS_T);
#pragma unroll
                for (int n = 0; n < 4; n++)
                    wmma::load_matrix_sync(bh[n], pB + n * 16 * LDS_T, LDS_T);
                // hi*hi
#pragma unroll
                for (int m = 0; m < 2; m++)
#pragma unroll
                    for (int n = 0; n < 4; n++)
                        wmma::mma_sync(acc[m][n], ah[m], bh[n], acc[m][n]);
                // lo*hi
#pragma unroll
                for (int m = 0; m < 2; m++)
                    wmma::load_matrix_sync(al[m], sAl + (wm * 32 + m * 16) * LDS_T + ko, LDS_T);
#pragma unroll
                for (int m = 0; m < 2; m++)
#pragma unroll
                    for (int n = 0; n < 4; n++)
                        wmma::mma_sync(acc[m][n], al[m], bh[n], acc[m][n]);
                // hi*lo
#pragma unroll
                for (int n = 0; n < 4; n++)
                    wmma::load_matrix_sync(bl[n], sBl + (wn * 64 + n * 16) * LDS_T + ko, LDS_T);
#pragma unroll
                for (int m = 0; m < 2; m++)
#pragma unroll
                    for (int n = 0; n < 4; n++)
                        wmma::mma_sync(acc[m][n], ah[m], bl[n], acc[m][n]);
            }
        }
    }

    // ---------------- epilogue: park accum in smem, fuse, store -------------
    __syncthreads();
    float* sT = (float*)dsm;         // 128 x LDS_F floats (staging smem reused)
#pragma unroll
    for (int m = 0; m < 2; m++)
#pragma unroll
        for (int n = 0; n < 4; n++)
            wmma::store_matrix_sync(sT + (wm * 32 + m * 16) * LDS_F + wn * 64 + n * 16,
                                    acc[m][n], LDS_F, wmma::mem_row_major);
    __syncthreads();

    const float nsv = *nsp;
    const int ey = par >> 1, ex = par & 1;

    if (CONVT) {
        // NHWC bf16 hi/lo out, oc fastest
        for (int lin = tid; lin < 16384; lin += 256) {
            int ocl = lin & 127, p = lin >> 7;
            int oc = obase + ocl;
            float v = sT[ocl * LDS_F + p] * g_d0[b * NC + oc];
            int ly = p >> 4, lx = p & 15;
            int gY = 2 * (tY0 + ly) + ey, gX = 2 * (tX0 + lx) + ex;
            v += noisec[gY * 64 + gX] * nsv + biasp[oc];
            v = act_lrelu_clamp(v) * g_s1[b * NC + oc];
            __nv_bfloat16 hi = __float2bfloat16(v);
            __nv_bfloat16 lo = __float2bfloat16(v - __bfloat162float(hi));
            size_t dst = ((size_t)(b * 64 + gY) * 64 + gX) * NC + oc;
            g_x1h[dst] = hi;
            g_x1l[dst] = lo;
        }
    } else {
        // NCHW fp32 out, px fastest
        for (int lin = tid; lin < 16384; lin += 256) {
            int p = lin & 127, ocl = lin >> 7;
            int oc = obase + ocl;
            float v = sT[ocl * LDS_F + p] * g_d1[b * NC + oc];
            int ly = p >> 4, lx = p & 15;
            int Y = tY0 + ly, X = tX0 + lx;
            v += noisec[Y * 64 + X] * nsv + biasp[oc];
            v = act_lrelu_clamp(v);
            xout[((size_t)(b * NC + oc) * 64 + Y) * 64 + X] = v;
        }
    }
}

// ---------------------------------------------------------------------------
// ToRGB + img upsample
// ---------------------------------------------------------------------------
__global__ void __launch_bounds__(256) torgb_kernel(
        const float* __restrict__ x2, const float* __restrict__ img,
        const float* __restrict__ brgb, float* __restrict__ imgout) {
    __shared__ float swm[3 * NC];
    int b = blockIdx.y;
    for (int i = threadIdx.x; i < 3 * NC; i += 256) swm[i] = g_wm[b * 3 * NC + i];
    __syncthreads();
    int pxl = blockIdx.x * 256 + threadIdx.x;
    int Y = pxl >> 6, X = pxl & 63;

    float a0 = 0.f, a1 = 0.f, a2 = 0.f;
    const float* xp = x2 + (size_t)b * NC * 4096 + pxl;
#pragma unroll 8
    for (int o = 0; o < NC; o++) {
        float xv = xp[(size_t)o * 4096];
        a0 += xv * swm[o];
        a1 += xv * swm[NC + o];
        a2 += xv * swm[2 * NC + o];
    }
    const float G[4] = {0.25f, 0.75f, 0.75f, 0.25f};
    float up0 = 0.f, up1 = 0.f, up2 = 0.f;
#pragma unroll
    for (int a = 0; a < 4; a++) {
        int yy = Y + a - 2;
        if (yy & 1) continue;
        int iy = yy >> 1;
        if (iy < 0 || iy > 31) continue;
#pragma unroll
        for (int bb = 0; bb < 4; bb++) {
            int xx = X + bb - 2;
            if (xx & 1) continue;
            int ix = xx >> 1;
            if (ix < 0 || ix > 31) continue;
            float cf = G[a] * G[bb];
            up0 += img[((size_t)(b * 3 + 0) * 32 + iy) * 32 + ix] * cf;
            up1 += img[((size_t)(b * 3 + 1) * 32 + iy) * 32 + ix] * cf;
            up2 += img[((size_t)(b * 3 + 2) * 32 + iy) * 32 + ix] * cf;
        }
    }
    float y0 = fminf(fmaxf(a0 + brgb[0], -CLAMPV), CLAMPV);
    float y1 = fminf(fmaxf(a1 + brgb[1], -CLAMPV), CLAMPV);
    float y2 = fminf(fmaxf(a2 + brgb[2], -CLAMPV), CLAMPV);
    imgout[((size_t)b * 3 + 0) * 4096 + pxl] = up0 + y0;
    imgout[((size_t)b * 3 + 1) * 4096 + pxl] = up1 + y1;
    imgout[((size_t)b * 3 + 2) * 4096 + pxl] = up2 + y2;
}

// ---------------------------------------------------------------------------
// Launch
// ---------------------------------------------------------------------------
#define SMEM_DYN 73728   // max(4*18432 staging, 128*132*4 epilogue = 67584)

extern "C" void kernel_launch(void* const* d_in, const int* in_sizes, int n_in,
                              void* d_out, int out_size) {
    (void)in_sizes; (void)n_in; (void)out_size;
    const float* x    = (const float*)d_in[0];
    const float* img  = (const float*)d_in[1];
    const float* ws   = (const float*)d_in[2];
    const float* a0w  = (const float*)d_in[3];
    const float* a0b  = (const float*)d_in[4];
    const float* w0   = (const float*)d_in[5];
    const float* b0   = (const float*)d_in[6];
    const float* ns0  = (const float*)d_in[7];
    const float* a1w  = (const float*)d_in[8];
    const float* a1b  = (const float*)d_in[9];
    const float* w1   = (const float*)d_in[10];
    const float* b1   = (const float*)d_in[11];
    const float* ns1  = (const float*)d_in[12];
    const float* arw  = (const float*)d_in[13];
    const float* arb  = (const float*)d_in[14];
    const float* wrgb = (const float*)d_in[15];
    const float* brgb = (const float*)d_in[16];
    const float* nc0  = (const float*)d_in[17];
    const float* nc1  = (const float*)d_in[18];

    float* xout   = (float*)d_out;
    float* imgout = (float*)d_out + XOUT_ELEMS;

    cudaFuncSetAttribute(mma_conv_kernel<1>, cudaFuncAttributeMaxDynamicSharedMemorySize, SMEM_DYN);
    cudaFuncSetAttribute(mma_conv_kernel<0>, cudaFuncAttributeMaxDynamicSharedMemorySize, SMEM_DYN);

    // prologue
    styles_kernel<<<dim3(NB, 3), NC>>>(ws, a0w, a0b, a1w, a1b, arw, arb);
    w2_kernel<<<NC, NC>>>(w0, w1);
    demod_kernel<<<dim3(NB, 2), NC>>>();
    wm_kernel<<<NB, NC>>>(wrgb);
    prep_w0eff_kernel<<<(NC * NC + 255) / 256, 256>>>(w0);
    prep_w1_kernel<<<(9 * NC * NC + 255) / 256, 256>>>(w1);
    prep_x0_kernel<<<dim3(16, 32, NB), 256>>>(x);

    // convT (+fused blur/noise0/bias0/act/s1) -> g_x1 NHWC bf16 hi/lo
    mma_conv_kernel<1><<<dim3(8, 16, NB), 256, SMEM_DYN>>>(nc0, ns0, b0, nullptr);

    // main 3x3 conv (+noise1/bias1/act) -> xout NCHW fp32
    mma_conv_kernel<0><<<dim3(32, 4, NB), 256, SMEM_DYN>>>(nc1, ns1, b1, xout);

    // img upsample + ToRGB
    torgb_kernel<<<dim3(16, NB), 256>>>(xout, img, brgb, imgout);
}